// round 1
// baseline (speedup 1.0000x reference)
#include <cuda_runtime.h>

// FilterEnhance: Y[b,f,t] = sum_{c,tau} W[f,c,tau] * X[b,c,t+tau-127] (zero pad)
// loss = sum_{b,f,t} (Y[b,f,t] - X[b, f%8, t])^2 / 8388608
//
// Round 1: scalar fp32 register-tiled SIMT kernel. FMA-pipe-bound by design.

#define NTHREADS 256
#define TT 128          // t positions per block
#define FT 32           // filters per block
#define XS_LEN 384      // TT + 254, padded to 384 (all entries initialized)
#define WS_LEN 256      // 255 taps + 1 zero pad (keeps float4 alignment)

__device__ double g_acc;

__global__ void k_zero() { g_acc = 0.0; }

__global__ void k_final(float* out) {
    // 16 (b) * 8 (c) * 8192 (t) * 8 (chunk mean) = 8388608
    out[0] = (float)(g_acc * (1.0 / 8388608.0));
}

__global__ __launch_bounds__(NTHREADS, 3)
void k_conv_loss(const float* __restrict__ X, const float* __restrict__ F) {
    __shared__ float Xs[8][XS_LEN];     // 12 KB
    __shared__ float Ws[FT][WS_LEN];    // 32 KB
    __shared__ float wsum[8];

    const int tid  = threadIdx.x;
    const int warp = tid >> 5;
    const int lane = tid & 31;
    const int t0 = blockIdx.x * TT;
    const int f0 = blockIdx.y * FT;
    const int b  = blockIdx.z;

    const float* Xb = X + (size_t)b * (8 * 8192);

    // Stage X window for all 8 channels: global t in [t0-127, t0+257)
    for (int idx = tid; idx < 8 * XS_LEN; idx += NTHREADS) {
        int c = idx / XS_LEN;
        int p = idx - c * XS_LEN;
        int tg = t0 - 127 + p;
        Xs[c][p] = (tg >= 0 && tg < 8192) ? Xb[c * 8192 + tg] : 0.0f;
    }

    float acc[4][4];
    #pragma unroll
    for (int i = 0; i < 4; i++)
        #pragma unroll
        for (int j = 0; j < 4; j++) acc[i][j] = 0.0f;

    const int fbase = warp << 2;        // this warp's 4 local filters

    for (int cs = 0; cs < 8; cs++) {
        __syncthreads();
        // Stage weights for channel cs: 32 filters x 255 taps (+1 zero pad)
        for (int idx = tid; idx < FT * WS_LEN; idx += NTHREADS) {
            int fl  = idx >> 8;
            int tau = idx & 255;
            Ws[fl][tau] = (tau < 255)
                ? F[((size_t)(f0 + fl) * 8 + cs) * 255 + tau] : 0.0f;
        }
        __syncthreads();

        // Rolling-window inner loop: per tau-quad, 5x LDS.128 + 64 FFMA
        const float* xrow = &Xs[cs][lane << 2];
        float4 cur = *(const float4*)xrow;
        #pragma unroll 4
        for (int tq = 0; tq < 64; tq++) {
            float4 nxt = *(const float4*)(xrow + (tq << 2) + 4);
            float x0 = cur.x, x1 = cur.y, x2 = cur.z, x3 = cur.w;
            float x4 = nxt.x, x5 = nxt.y, x6 = nxt.z;
            #pragma unroll
            for (int i = 0; i < 4; i++) {
                float4 wv = *(const float4*)&Ws[fbase + i][tq << 2];
                acc[i][0] += wv.x * x0;
                acc[i][1] += wv.x * x1;
                acc[i][2] += wv.x * x2;
                acc[i][3] += wv.x * x3;
                acc[i][0] += wv.y * x1;
                acc[i][1] += wv.y * x2;
                acc[i][2] += wv.y * x3;
                acc[i][3] += wv.y * x4;
                acc[i][0] += wv.z * x2;
                acc[i][1] += wv.z * x3;
                acc[i][2] += wv.z * x4;
                acc[i][3] += wv.z * x5;
                acc[i][0] += wv.w * x3;
                acc[i][1] += wv.w * x4;
                acc[i][2] += wv.w * x5;
                acc[i][3] += wv.w * x6;
            }
            cur = nxt;
        }
    }

    // Epilogue: diff vs X[b, f%8, t], square, reduce
    float ssd = 0.0f;
    #pragma unroll
    for (int i = 0; i < 4; i++) {
        int cf = (fbase + i) & 7;       // f0 is a multiple of 32, so (f%8) == (local%8)
        #pragma unroll
        for (int j = 0; j < 4; j++) {
            float d = acc[i][j] - Xs[cf][127 + (lane << 2) + j];
            ssd += d * d;
        }
    }
    #pragma unroll
    for (int o = 16; o; o >>= 1)
        ssd += __shfl_xor_sync(0xffffffffu, ssd, o);

    if (lane == 0) wsum[warp] = ssd;
    __syncthreads();
    if (tid == 0) {
        float s = 0.0f;
        #pragma unroll
        for (int w = 0; w < 8; w++) s += wsum[w];
        atomicAdd(&g_acc, (double)s);
    }
}

extern "C" void kernel_launch(void* const* d_in, const int* in_sizes, int n_in,
                              void* d_out, int out_size) {
    const float* X = (const float*)d_in[0];
    const float* F = (const float*)d_in[1];
    // Defensive: identify inputs by element count
    if (n_in >= 2 && in_sizes[0] == 16 * 64 * 8 * 255) {
        const float* t = X; X = F; F = t;
    }

    k_zero<<<1, 1>>>();
    dim3 grid(8192 / TT, 1024 / FT, 16);   // (64, 32, 16) = 32768 blocks
    k_conv_loss<<<grid, NTHREADS>>>(X, F);
    k_final<<<1, 1>>>((float*)d_out);
}

// round 2
// speedup vs baseline: 1.0430x; 1.0430x over previous
#include <cuda_runtime.h>

// FilterEnhance: Y[b,f,t] = sum_{c,tau} W[f,c,tau] * X[b,c,t+tau-127] (zero pad)
// loss = sum_{b,f,t} (Y[b,f,t] - X[b, f%8, t])^2 / 8388608
//
// Round 2: packed fp32 (fma.rn.f32x2) over filter pairs -> half the fma-pipe slots.

#define NTHREADS 256
#define TT 128          // t positions per block
#define FT 32           // filters per block
#define XS_LEN 384      // TT + 254, padded to 384 (all entries initialized)

typedef unsigned long long u64;

__device__ double g_acc;   // static-init 0; k_final re-zeroes after each read

__device__ __forceinline__ u64 fma2(u64 a, u64 b, u64 c) {
    u64 d;
    asm("fma.rn.f32x2 %0, %1, %2, %3;" : "=l"(d) : "l"(a), "l"(b), "l"(c));
    return d;
}
__device__ __forceinline__ u64 dup2(float x) {
    u64 d;
    asm("mov.b64 %0, {%1, %1};" : "=l"(d) : "f"(x));
    return d;
}
__device__ __forceinline__ float2 unpack2(u64 v) {
    float2 r;
    asm("mov.b64 {%0, %1}, %2;" : "=f"(r.x), "=f"(r.y) : "l"(v));
    return r;
}

__global__ void k_final(float* out) {
    // 16 (b) * 8 (c) * 8192 (t) * 8 (chunk mean) = 8388608
    out[0] = (float)(g_acc * (1.0 / 8388608.0));
    g_acc = 0.0;   // reset for next replay (graph-safe, deterministic)
}

__global__ __launch_bounds__(NTHREADS, 3)
void k_conv_loss(const float* __restrict__ X, const float* __restrict__ F) {
    __shared__ float Xs[8][XS_LEN];      // 12 KB
    __shared__ float Ws2[16][512];       // 32 KB: [fpair][tau*2 + half], tau 0..255 (255 = zero pad)
    __shared__ float wsum[8];

    const int tid  = threadIdx.x;
    const int warp = tid >> 5;
    const int lane = tid & 31;
    const int t0 = blockIdx.x * TT;
    const int f0 = blockIdx.y * FT;
    const int b  = blockIdx.z;

    const float* Xb = X + (size_t)b * (8 * 8192);

    // Stage X window for all 8 channels: global t in [t0-127, t0+257)
    for (int idx = tid; idx < 8 * XS_LEN; idx += NTHREADS) {
        int c = idx / XS_LEN;
        int p = idx - c * XS_LEN;
        int tg = t0 - 127 + p;
        Xs[c][p] = (tg >= 0 && tg < 8192) ? Xb[c * 8192 + tg] : 0.0f;
    }

    // 2 filter-pairs per warp, 4 t per lane -> 8 packed accumulators
    u64 acc[2][4];
    #pragma unroll
    for (int i = 0; i < 2; i++)
        #pragma unroll
        for (int j = 0; j < 4; j++) acc[i][j] = 0ull;

    const int fp0 = warp << 1;           // this warp's first fpair (filters warp*4 .. warp*4+3)

    for (int cs = 0; cs < 8; cs++) {
        __syncthreads();
        // Stage weights for channel cs, interleaved by filter pair:
        // Ws2[fl>>1][tau*2 + (fl&1)] = W[f0+fl][cs][tau]
        for (int idx = tid; idx < FT * 256; idx += NTHREADS) {
            int fl  = idx >> 8;
            int tau = idx & 255;
            float v = (tau < 255)
                ? F[((size_t)(f0 + fl) * 8 + cs) * 255 + tau] : 0.0f;
            Ws2[fl >> 1][tau * 2 + (fl & 1)] = v;
        }
        __syncthreads();

        const float* xrow = &Xs[cs][lane << 2];
        float4 cur = *(const float4*)xrow;
        u64 xd0 = dup2(cur.x), xd1 = dup2(cur.y), xd2 = dup2(cur.z), xd3 = dup2(cur.w);

        #pragma unroll 2
        for (int tq = 0; tq < 64; tq++) {
            float4 nxt = *(const float4*)(xrow + (tq << 2) + 4);
            u64 xd4 = dup2(nxt.x), xd5 = dup2(nxt.y), xd6 = dup2(nxt.z);

            #pragma unroll
            for (int i = 0; i < 2; i++) {
                const float* wrow = &Ws2[fp0 + i][tq << 3];
                ulonglong2 wA = *(const ulonglong2*)wrow;        // tap pairs tau0, tau1
                ulonglong2 wB = *(const ulonglong2*)(wrow + 4);  // tap pairs tau2, tau3
                acc[i][0] = fma2(wA.x, xd0, acc[i][0]);
                acc[i][1] = fma2(wA.x, xd1, acc[i][1]);
                acc[i][2] = fma2(wA.x, xd2, acc[i][2]);
                acc[i][3] = fma2(wA.x, xd3, acc[i][3]);
                acc[i][0] = fma2(wA.y, xd1, acc[i][0]);
                acc[i][1] = fma2(wA.y, xd2, acc[i][1]);
                acc[i][2] = fma2(wA.y, xd3, acc[i][2]);
                acc[i][3] = fma2(wA.y, xd4, acc[i][3]);
                acc[i][0] = fma2(wB.x, xd2, acc[i][0]);
                acc[i][1] = fma2(wB.x, xd3, acc[i][1]);
                acc[i][2] = fma2(wB.x, xd4, acc[i][2]);
                acc[i][3] = fma2(wB.x, xd5, acc[i][3]);
                acc[i][0] = fma2(wB.y, xd3, acc[i][0]);
                acc[i][1] = fma2(wB.y, xd4, acc[i][1]);
                acc[i][2] = fma2(wB.y, xd5, acc[i][2]);
                acc[i][3] = fma2(wB.y, xd6, acc[i][3]);
            }
            xd0 = xd4; xd1 = xd5; xd2 = xd6; xd3 = dup2(nxt.w);
        }
    }

    // Epilogue: diff vs X[b, f%8, t], square, reduce.
    // fpair (fp0+i) holds filters lf0 = warp*4 + i*2 (lo half) and lf0+1 (hi half).
    float ssd = 0.0f;
    #pragma unroll
    for (int i = 0; i < 2; i++) {
        int lf0 = (warp << 2) + (i << 1);
        int c0 = lf0 & 7;            // f0 multiple of 32 -> f%8 == local%8
        int c1 = (lf0 + 1) & 7;
        #pragma unroll
        for (int j = 0; j < 4; j++) {
            float2 y = unpack2(acc[i][j]);
            float xv0 = Xs[c0][127 + (lane << 2) + j];
            float xv1 = Xs[c1][127 + (lane << 2) + j];
            float d0 = y.x - xv0;
            float d1 = y.y - xv1;
            ssd += d0 * d0;
            ssd += d1 * d1;
        }
    }
    #pragma unroll
    for (int o = 16; o; o >>= 1)
        ssd += __shfl_xor_sync(0xffffffffu, ssd, o);

    if (lane == 0) wsum[warp] = ssd;
    __syncthreads();
    if (tid == 0) {
        float s = 0.0f;
        #pragma unroll
        for (int w = 0; w < 8; w++) s += wsum[w];
        atomicAdd(&g_acc, (double)s);
    }
}

extern "C" void kernel_launch(void* const* d_in, const int* in_sizes, int n_in,
                              void* d_out, int out_size) {
    const float* X = (const float*)d_in[0];
    const float* F = (const float*)d_in[1];
    if (n_in >= 2 && in_sizes[0] == 16 * 64 * 8 * 255) {
        const float* t = X; X = F; F = t;
    }

    dim3 grid(8192 / TT, 1024 / FT, 16);   // (64, 32, 16) = 32768 blocks
    k_conv_loss<<<grid, NTHREADS>>>(X, F);
    k_final<<<1, 1>>>((float*)d_out);      // reads + resets g_acc
}

// round 4
// speedup vs baseline: 8.3356x; 7.9920x over previous
#include <cuda_runtime.h>
#include <cuda_bf16.h>

// FilterEnhance via bf16 implicit-GEMM conv using baseline-ISA tensor path
// (mma.sync.aligned.m16n8k16 + ldmatrix) -- compute_100-compatible, no tcgen05.
//
// Y[f,t] = sum_{c,tau} W[f,c,tau] * Xpad[b,c,t+tau-127]
// loss = sum (Y - X[b,f%8,t])^2 / 8388608
//
// CTA tile: 128 filters x 128 t. K-loop: 8 channels x 4 tau-quarters of 64.
// A: pre-swizzled bf16 weights in GMEM (k_prep) -> cp.async, double-buffered.
// B: Hankel fragments read directly from per-channel parity-pair x-windows.

typedef unsigned int u32;
typedef unsigned long long u64;

__device__ double g_acc;                     // static 0; k_final resets after read
__device__ uint4 g_Wsw4[8 * 8 * 4 * 1024];   // 4MB: [ftile][c][q] 16KB swizzled A-tiles

// ---------------- helpers ----------------
__device__ __forceinline__ u32 smem_u32(const void* p) {
    u32 a;
    asm("{ .reg .u64 t; cvta.to.shared.u64 t, %1; cvt.u32.u64 %0, t; }" : "=r"(a) : "l"(p));
    return a;
}
__device__ __forceinline__ u64 to_global(const void* p) {
    u64 g;
    asm("cvta.to.global.u64 %0, %1;" : "=l"(g) : "l"(p));
    return g;
}
__device__ __forceinline__ void cpa16(u32 dst, u64 gsrc) {
    asm volatile("cp.async.cg.shared.global [%0], [%1], 16;" :: "r"(dst), "l"(gsrc) : "memory");
}
#define CP_COMMIT() asm volatile("cp.async.commit_group;" ::: "memory")
#define CP_WAIT(n)  asm volatile("cp.async.wait_group %0;" :: "n"(n) : "memory")

__device__ __forceinline__ void ldmatrix_x4(u32& a0, u32& a1, u32& a2, u32& a3, u32 addr) {
    asm volatile("ldmatrix.sync.aligned.m8n8.x4.shared.b16 {%0,%1,%2,%3}, [%4];"
                 : "=r"(a0), "=r"(a1), "=r"(a2), "=r"(a3) : "r"(addr));
}
__device__ __forceinline__ void mma16816(float& d0, float& d1, float& d2, float& d3,
                                         u32 a0, u32 a1, u32 a2, u32 a3,
                                         u32 b0, u32 b1) {
    asm volatile("mma.sync.aligned.m16n8k16.row.col.f32.bf16.bf16.f32 "
                 "{%0,%1,%2,%3}, {%4,%5,%6,%7}, {%8,%9}, {%0,%1,%2,%3};"
                 : "+f"(d0), "+f"(d1), "+f"(d2), "+f"(d3)
                 : "r"(a0), "r"(a1), "r"(a2), "r"(a3), "r"(b0), "r"(b1));
}

// ---------------- SMEM layout (from 1024-aligned base) ----------------
#define OFF_A0  0u          // A double buffer: 2 x 16384
#define OFF_XW  32768u      // 8 ch x (192 E + 192 O) u32 = 12288 B; ch stride 1536 B
#define OFF_XC  45056u      // 8 x 132 fp32 = 4224 B
#define OFF_WS  49280u      // 8 warp sums
#define SMEM_BYTES (49280u + 64u + 1024u)

// ---------------- prep: pre-swizzled bf16 weight tiles ----------------
// Tile tix = (ft*8 + c)*4 + q : 128 filters x 64 taps bf16, row=filter (128B),
// SW128-swizzled byte offsets so ldmatrix (16B granularity) is conflict-free.
__global__ void k_prep(const float* __restrict__ F) {
    __nv_bfloat16* W = (__nv_bfloat16*)g_Wsw4;
    const int total = 8 * 8 * 4 * 8192;
    for (int e = blockIdx.x * blockDim.x + threadIdx.x; e < total; e += gridDim.x * blockDim.x) {
        int tix = e >> 13;
        int off = e & 8191;
        int q = tix & 3, c = (tix >> 2) & 7, ft = tix >> 5;
        int fl = off >> 6, k = off & 63;
        int tau = q * 64 + k;
        float v = (tau < 255) ? F[((size_t)(ft * 128 + fl) * 8 + c) * 255 + tau] : 0.0f;
        u32 sb = (u32)(fl * 128 + k * 2);
        sb ^= (sb >> 3) & 0x70;
        W[(size_t)tix * 8192 + (sb >> 1)] = __float2bfloat16(v);
    }
}

__global__ void k_final(float* out) {
    out[0] = (float)(g_acc * (1.0 / 8388608.0));
    g_acc = 0.0;
}
__global__ void k_nop() {}

// ---------------- main ----------------
__global__ __launch_bounds__(256, 2)
void k_main(const float* __restrict__ X) {
    extern __shared__ char smem_raw[];
    u32 raw = smem_u32(smem_raw);
    u32 sb = (raw + 1023u) & ~1023u;
    char* base = smem_raw + (sb - raw);

    u32*   xw   = (u32*)(base + OFF_XW);
    float* xc   = (float*)(base + OFF_XC);
    float* wsum = (float*)(base + OFF_WS);

    const int tid = threadIdx.x, wid = tid >> 5, lane = tid & 31;
    const int warp_m = wid & 1;        // 2 x 64 filters
    const int warp_n = wid >> 1;       // 4 x 32 t
    const int t0 = blockIdx.x * 128;
    const int ft = blockIdx.y;
    const int b  = blockIdx.z;
    const float* Xb = X + (size_t)b * 8 * 8192;

    // Stage bf16 x-windows (all 8 channels), parity-pair layout.
    // window j in [0,384): x[j] = Xpad[t0 + j - 127]
    for (int idx = tid; idx < 8 * 192; idx += 256) {
        int c = idx / 192, i = idx - c * 192;
        int t = t0 + 2 * i - 127;
        float a0 = (t >= 0 && t < 8192)     ? Xb[c * 8192 + t]     : 0.0f;
        float a1 = (t + 1 >= 0 && t + 1 < 8192) ? Xb[c * 8192 + t + 1] : 0.0f;
        float a2 = (t + 2 >= 0 && t + 2 < 8192) ? Xb[c * 8192 + t + 2] : 0.0f;
        u32 b0 = (u32)__bfloat16_as_ushort(__float2bfloat16(a0));
        u32 b1 = (u32)__bfloat16_as_ushort(__float2bfloat16(a1));
        u32 b2 = (u32)__bfloat16_as_ushort(__float2bfloat16(a2));
        xw[c * 384 + i]       = (b1 << 16) | b0;   // E: (x[2i], x[2i+1])
        xw[c * 384 + 192 + i] = (b2 << 16) | b1;   // O: (x[2i+1], x[2i+2])
    }
    // fp32 compare tile, padded stride 132
    for (int idx = tid; idx < 8 * 128; idx += 256) {
        int c = idx >> 7, j = idx & 127;
        xc[c * 132 + j] = Xb[c * 8192 + t0 + j];
    }

    const u64 wg = to_global(g_Wsw4);
    const u32 abuf[2] = { sb + OFF_A0, sb + OFF_A0 + 16384u };

    // prologue: chunk 0 -> buf 0
    {
        int tix = (ft * 8 + 0) * 4 + 0;
        u64 src = wg + (u64)tix * 16384u;
        #pragma unroll
        for (int i = 0; i < 4; i++) {
            int e = tid + i * 256;
            cpa16(abuf[0] + (u32)e * 16u, src + (u64)e * 16u);
        }
        CP_COMMIT();
    }

    float acc[4][4][4];
    #pragma unroll
    for (int mt = 0; mt < 4; mt++)
        #pragma unroll
        for (int nt = 0; nt < 4; nt++)
            #pragma unroll
            for (int r = 0; r < 4; r++) acc[mt][nt][r] = 0.0f;

    // per-thread constants
    const int sB = (lane & 3) * 2 + warp_n * 32 + (lane >> 2);   // B frag base offset
    const int pB = sB & 1;                                       // parity (fixed)
    const u32 a_lanecol = (u32)((lane >> 4) * 16);               // 16B half-select
    const int a_lanerow = warp_m * 64 + (lane & 15);

    for (int ci = 0; ci < 32; ci++) {
        const int buf = ci & 1, c = ci >> 2, q = ci & 3;

        if (ci < 31) {
            int cn = ci + 1;
            int tix = (ft * 8 + (cn >> 2)) * 4 + (cn & 3);
            u64 src = wg + (u64)tix * 16384u;
            u32 dst = abuf[cn & 1];
            #pragma unroll
            for (int i = 0; i < 4; i++) {
                int e = tid + i * 256;
                cpa16(dst + (u32)e * 16u, src + (u64)e * 16u);
            }
            CP_COMMIT();
            CP_WAIT(1);
        } else {
            CP_WAIT(0);
        }
        __syncthreads();

        const u32 atile = abuf[buf];
        const u32* xwc = xw + c * 384 + pB * 192;   // parity-selected array
        const int sbase = sB + q * 64;

        #pragma unroll
        for (int ks = 0; ks < 4; ks++) {
            u32 bf0[4], bf1[4];
            #pragma unroll
            for (int nt = 0; nt < 4; nt++) {
                int s0 = sbase + ks * 16 + nt * 8;
                int w0 = s0 >> 1;
                bf0[nt] = xwc[w0];
                bf1[nt] = xwc[w0 + 4];
            }
            #pragma unroll
            for (int mt = 0; mt < 4; mt++) {
                u32 byteoff = (u32)((a_lanerow + mt * 16) * 128) + (u32)(ks * 32) + a_lanecol;
                byteoff ^= (byteoff >> 3) & 0x70;
                u32 a0, a1, a2, a3;
                ldmatrix_x4(a0, a1, a2, a3, atile + byteoff);
                #pragma unroll
                for (int nt = 0; nt < 4; nt++)
                    mma16816(acc[mt][nt][0], acc[mt][nt][1], acc[mt][nt][2], acc[mt][nt][3],
                             a0, a1, a2, a3, bf0[nt], bf1[nt]);
            }
        }
        __syncthreads();
    }

    // Epilogue: D rows r0=lane/4 and r0+8 share channel ch=(lane/4)%8=lane/4.
    float ssd = 0.0f;
    const int ch = lane >> 2;
    const int n0 = warp_n * 32 + (lane & 3) * 2;
    #pragma unroll
    for (int nt = 0; nt < 4; nt++) {
        float xv0 = xc[ch * 132 + n0 + nt * 8];
        float xv1 = xc[ch * 132 + n0 + nt * 8 + 1];
        #pragma unroll
        for (int mt = 0; mt < 4; mt++) {
            float d0 = acc[mt][nt][0] - xv0;
            float d1 = acc[mt][nt][1] - xv1;
            float d2 = acc[mt][nt][2] - xv0;
            float d3 = acc[mt][nt][3] - xv1;
            ssd += d0 * d0 + d1 * d1 + d2 * d2 + d3 * d3;
        }
    }
    #pragma unroll
    for (int o = 16; o; o >>= 1)
        ssd += __shfl_xor_sync(0xffffffffu, ssd, o);
    if (lane == 0) wsum[wid] = ssd;
    __syncthreads();
    if (tid == 0) {
        float s = 0.0f;
        #pragma unroll
        for (int w = 0; w < 8; w++) s += wsum[w];
        atomicAdd(&g_acc, (double)s);
    }
}

extern "C" void kernel_launch(void* const* d_in, const int* in_sizes, int n_in,
                              void* d_out, int out_size) {
    const float* X = (const float*)d_in[0];
    const float* F = (const float*)d_in[1];
    if (n_in >= 2 && in_sizes[0] == 16 * 64 * 8 * 255) {
        const float* t = X; X = F; F = t;
    }

    static int configured = 0;
    if (!configured) {
        cudaFuncSetAttribute(k_main, cudaFuncAttributeMaxDynamicSharedMemorySize,
                             (int)SMEM_BYTES);
        configured = 1;
    }

    k_prep<<<256, 256>>>(F);
    dim3 grid(64, 8, 16);                      // (t-tiles, f-tiles, b) = 8192 CTAs
    k_main<<<grid, 256, SMEM_BYTES>>>(X);
    k_final<<<1, 1>>>((float*)d_out);
    k_nop<<<1, 1>>>();                         // 4 launches/replay -> ncu -s 5 lands on k_main
}